// round 13
// baseline (speedup 1.0000x reference)
#include <cuda_runtime.h>
#include <cuda_fp16.h>
#include <cstdint>

// DistTokenMix: out[b,i,d] = sum_j h[b,j,d] * alpha[spd[i,j], d]
//  = sum_{k<7} mask_k @ (h * (alpha_k - alpha_7)) + alpha_7[d] * colsum_j(h[b,:,d])
// via portable mma.sync.m16n8k16 (harness targets plain sm_103: no tcgen05).
// B=8, N=4096, D=64, buckets=8; n = b*64+d in [0,512).

#define NN 4096
#define BB 8
#define DD 64

__device__ unsigned int   g_bpk[NN * (NN / 4)];  // [i][j/4] bucket bytes
__device__ unsigned short g_hT[512 * NN];        // fp16 hT[n][j]
__device__ unsigned int   g_scl[7 * 512];        // half2{da,da}: dalpha[k][n]
__device__ float          g_base[512];           // alpha7[d]*colsum[b,d]

// ---------------------------------------------------------------------------
__global__ void __launch_bounds__(256) convert_spd_kernel(const unsigned int* __restrict__ spd_raw) {
    __shared__ int s_is64;
    if (threadIdx.x == 0) {
        unsigned int orv = 0;
#pragma unroll
        for (int t = 1; t < 64; t += 2) orv |= spd_raw[t];
        s_is64 = (orv == 0u) ? 1 : 0;      // int64 small values: odd words all 0
    }
    __syncthreads();
    const bool is64 = (s_is64 != 0);
    int t = blockIdx.x * blockDim.x + threadIdx.x;   // over NN*(NN/4)
    int jw = t & 1023, i = t >> 10;
    unsigned int w = 0;
#pragma unroll
    for (int c = 0; c < 4; ++c) {
        long long off = (long long)i * NN + 4 * jw + c;
        unsigned int v = is64 ? spd_raw[off * 2] : spd_raw[off];
        w |= (v & 7u) << (8 * c);
    }
    g_bpk[t] = w;
}

// ---------------------------------------------------------------------------
__global__ void __launch_bounds__(256) transpose_h_kernel(const float* __restrict__ h) {
    __shared__ float tile[64 * 65];
    const int b = blockIdx.x >> 6, j0 = (blockIdx.x & 63) * 64, tid = threadIdx.x;
#pragma unroll
    for (int r = 0; r < 16; ++r) {
        int lin = r * 256 + tid, d = lin & 63, jj = lin >> 6;
        tile[jj * 65 + d] = h[((size_t)b * NN + j0 + jj) * DD + d];
    }
    __syncthreads();
#pragma unroll
    for (int r = 0; r < 16; ++r) {
        int lin = r * 256 + tid, jj = lin & 63, d = lin >> 6;
        g_hT[(size_t)(b * 64 + d) * NN + j0 + jj] =
            __half_as_ushort(__float2half_rn(tile[jj * 65 + d]));
    }
}

// ---------------------------------------------------------------------------
// colsum + base + dalpha half2 tables. Grid = 8 (one block per b).
__global__ void __launch_bounds__(256) prep_kernel(const float* __restrict__ h,
                                                   const float* __restrict__ alpha) {
    __shared__ float red[256];
    const int b = blockIdx.x, tid = threadIdx.x, d = tid & 63, jg = tid >> 6;
    float s = 0.f;
    for (int j = jg; j < NN; j += 4) s += h[((size_t)b * NN + j) * DD + d];
    red[tid] = s;
    __syncthreads();
    if (jg == 0)
        g_base[b * 64 + d] = alpha[7 * 64 + d] * (red[d] + red[64 + d] + red[128 + d] + red[192 + d]);
    if (b == 0) {
        for (int t = tid; t < 7 * 512; t += 256) {
            int k = t >> 9, dd = t & 63;
            unsigned short us = __half_as_ushort(
                __float2half_rn(alpha[k * 64 + dd] - alpha[7 * 64 + dd]));
            g_scl[t] = (unsigned)us | ((unsigned)us << 16);
        }
    }
}

// ---------------------------------------------------------------------------
static __device__ __forceinline__ void mma16816(float* c, unsigned a0, unsigned a1,
                                                unsigned a2, unsigned a3,
                                                unsigned b0, unsigned b1) {
    asm volatile(
        "mma.sync.aligned.m16n8k16.row.col.f32.f16.f16.f32 "
        "{%0,%1,%2,%3},{%4,%5,%6,%7},{%8,%9},{%0,%1,%2,%3};"
        : "+f"(c[0]), "+f"(c[1]), "+f"(c[2]), "+f"(c[3])
        : "r"(a0), "r"(a1), "r"(a2), "r"(a3), "r"(b0), "r"(b1));
}
static __device__ __forceinline__ unsigned hmul2(unsigned a, unsigned b) {
    unsigned r;
    asm("mul.rn.f16x2 %0,%1,%2;" : "=r"(r) : "r"(a), "r"(b));
    return r;
}

// ---------------------------------------------------------------------------
// Main: grid 256 (i-tiles of 16), 256 thr. Warp w owns n in [w*64, w*64+64);
// lane (g = l>>2, tq = l&3). Per 16-j chunk: 4 bucket LDG + 16 hT LDG (reused
// across 7 buckets); per k: A-frag by byte compare, B = hT regs * dalpha half2.
// All operands from L2-resident globals; no smem, no syncs.
// ---------------------------------------------------------------------------
__global__ void __launch_bounds__(256, 1) mix_mma_kernel(float* __restrict__ out) {
    const int tid = threadIdx.x, w = tid >> 5, l = tid & 31;
    const int g = l >> 2, tq = l & 3;
    const int i0 = blockIdx.x * 16;
    const int sh2 = (tq & 1) * 16;

    // preload per-lane dalpha half2 scales: n = w*64 + t*8 + g
    unsigned scl[7][8];
#pragma unroll
    for (int k = 0; k < 7; ++k)
#pragma unroll
        for (int t = 0; t < 8; ++t)
            scl[k][t] = g_scl[k * 512 + w * 64 + t * 8 + g];

    float acc[8][4];
#pragma unroll
    for (int t = 0; t < 8; ++t)
#pragma unroll
        for (int q = 0; q < 4; ++q) acc[t][q] = 0.f;

    const unsigned int* bp0 = g_bpk + (size_t)(i0 + g) * 1024 + (tq >> 1);
    const unsigned int* bp8 = g_bpk + (size_t)(i0 + g + 8) * 1024 + (tq >> 1);
    const unsigned short* hb = g_hT + (size_t)(w * 64 + g) * NN + 2 * tq;

    for (int jc = 0; jc < 256; ++jc) {
        const unsigned w0 = bp0[jc * 4], w1 = bp0[jc * 4 + 2];
        const unsigned w2 = bp8[jc * 4], w3 = bp8[jc * 4 + 2];
        unsigned hr[16];
#pragma unroll
        for (int t = 0; t < 8; ++t) {
            const unsigned short* p = hb + (size_t)t * 8 * NN + jc * 16;
            hr[2 * t]     = *(const unsigned int*)p;
            hr[2 * t + 1] = *(const unsigned int*)(p + 8);
        }
        const unsigned e0 = (w0 >> sh2) & 0xFF, e1 = (w0 >> (sh2 + 8)) & 0xFF;
        const unsigned e2 = (w1 >> sh2) & 0xFF, e3 = (w1 >> (sh2 + 8)) & 0xFF;
        const unsigned f0 = (w2 >> sh2) & 0xFF, f1 = (w2 >> (sh2 + 8)) & 0xFF;
        const unsigned f2 = (w3 >> sh2) & 0xFF, f3 = (w3 >> (sh2 + 8)) & 0xFF;

#pragma unroll
        for (int k = 0; k < 7; ++k) {
            const unsigned kk = (unsigned)k;
            // A frag: mask(i,j) in fp16 {0,1}. a0: row g, cols 2tq,2tq+1;
            // a1: row g+8 same cols; a2: row g cols+8; a3: row g+8 cols+8.
            const unsigned a0 = (e0 == kk ? 0x3C00u : 0u) | (e1 == kk ? 0x3C000000u : 0u);
            const unsigned a1 = (f0 == kk ? 0x3C00u : 0u) | (f1 == kk ? 0x3C000000u : 0u);
            const unsigned a2 = (e2 == kk ? 0x3C00u : 0u) | (e3 == kk ? 0x3C000000u : 0u);
            const unsigned a3 = (f2 == kk ? 0x3C00u : 0u) | (f3 == kk ? 0x3C000000u : 0u);
#pragma unroll
            for (int t = 0; t < 8; ++t) {
                const unsigned b0 = hmul2(hr[2 * t], scl[k][t]);
                const unsigned b1 = hmul2(hr[2 * t + 1], scl[k][t]);
                mma16816(acc[t], a0, a1, a2, a3, b0, b1);
            }
        }
    }

    // epilogue: D rows = i (g, g+8), cols = n-in-tile (2tq, 2tq+1); b = w.
#pragma unroll
    for (int t = 0; t < 8; ++t) {
        const int n0 = w * 64 + t * 8 + 2 * tq;
        const float2 base = *(const float2*)&g_base[n0];
        const int dcol = t * 8 + 2 * tq;
        float2 v0 = make_float2(acc[t][0] + base.x, acc[t][1] + base.y);
        float2 v1 = make_float2(acc[t][2] + base.x, acc[t][3] + base.y);
        *(float2*)&out[((size_t)w * NN + i0 + g) * DD + dcol]     = v0;
        *(float2*)&out[((size_t)w * NN + i0 + g + 8) * DD + dcol] = v1;
    }
}

// ---------------------------------------------------------------------------
extern "C" void kernel_launch(void* const* d_in, const int* in_sizes, int n_in,
                              void* d_out, int out_size) {
    const float* h = nullptr;
    const void*  spd = nullptr;
    const float* alpha = nullptr;
    for (int i = 0; i < n_in; ++i) {
        if (in_sizes[i] == BB * NN * DD)      h     = (const float*)d_in[i];
        else if (in_sizes[i] == NN * NN)      spd   = (const void*)d_in[i];
        else if (in_sizes[i] == 8 * DD)       alpha = (const float*)d_in[i];
    }

    convert_spd_kernel<<<NN * (NN / 4) / 256, 256>>>((const unsigned int*)spd);
    transpose_h_kernel<<<BB * 64, 256>>>(h);
    prep_kernel<<<BB, 256>>>(h, alpha);
    mix_mma_kernel<<<NN / 16, 256>>>((float*)d_out);
}

// round 14
// speedup vs baseline: 1.4049x; 1.4049x over previous
#include <cuda_runtime.h>
#include <cuda_fp16.h>
#include <cstdint>

// DistTokenMix: out[b,i,d] = sum_j h[b,j,d] * alpha[spd[i,j], d]
//  = sum_{k<7} mask_k @ (h * (alpha_k - alpha_7)) + alpha_7[d]*colsum_j(h[b,:,d])
// Portable mma.sync.m16n8k16 (plain sm_103 target: no tcgen05).
// B=8, N=4096, D=64, buckets=8; n = b*64+d in [0,512).

#define NN 4096
#define BB 8
#define DD 64

// Buckets as fp16 pairs, chunk layout: idx ((i*256 + jc)*4 + tq) ->
//   .x = half2(spd(i, 16jc+2tq), +1),  .y = half2(16jc+2tq+8, +9)      (32 MB)
__device__ uint2 g_bph[(size_t)NN * 1024];
// hT fp16, same chunk layout over n: ((n*256 + jc)*4 + tq) -> 4 j values (8 MB)
__device__ uint2 g_hT2[(size_t)512 * 1024];
__device__ unsigned int g_scl[7 * 512];   // half2{da,da}, da = alpha_k - alpha_7
__device__ float g_base[512];             // alpha7[d] * colsum[b,d]

// ---------------------------------------------------------------------------
// spd (int64 OR int32, runtime-detected) -> fp16 bucket-pair table.
// ---------------------------------------------------------------------------
__global__ void __launch_bounds__(256) convert_spd_kernel(const unsigned int* __restrict__ spd_raw) {
    __shared__ int s_is64;
    if (threadIdx.x == 0) {
        unsigned int orv = 0;
#pragma unroll
        for (int t = 1; t < 64; t += 2) orv |= spd_raw[t];
        s_is64 = (orv == 0u) ? 1 : 0;     // int64 small values: odd words all 0
    }
    __syncthreads();
    const bool is64 = (s_is64 != 0);
    size_t idx = (size_t)blockIdx.x * 256 + threadIdx.x;   // over NN*1024
    int i  = (int)(idx >> 10);
    int e  = (int)(idx & 1023);
    int jc = e >> 2, tq = e & 3;
    int j0 = jc * 16 + 2 * tq;
    unsigned v[4];
#pragma unroll
    for (int c = 0; c < 4; ++c) {
        int j = j0 + ((c >> 1) * 8) + (c & 1);             // j0, j0+1, j0+8, j0+9
        long long off = (long long)i * NN + j;
        v[c] = (is64 ? spd_raw[off * 2] : spd_raw[off]) & 7u;
    }
    uint2 r;
    __half2 x = __floats2half2_rn((float)v[0], (float)v[1]);
    __half2 y = __floats2half2_rn((float)v[2], (float)v[3]);
    r.x = *(unsigned*)&x;
    r.y = *(unsigned*)&y;
    g_bph[idx] = r;
}

// ---------------------------------------------------------------------------
// h[b,j,d] f32 -> g_hT2 fp16 chunk layout.
// ---------------------------------------------------------------------------
__global__ void __launch_bounds__(256) transpose_h_kernel(const float* __restrict__ h) {
    __shared__ float tile[64 * 65];       // [jj][d]
    const int b = blockIdx.x >> 6, j0 = (blockIdx.x & 63) * 64, tid = threadIdx.x;
#pragma unroll
    for (int r = 0; r < 16; ++r) {
        int lin = r * 256 + tid, d = lin & 63, jj = lin >> 6;
        tile[jj * 65 + d] = h[((size_t)b * NN + j0 + jj) * DD + d];
    }
    __syncthreads();
    // outputs: 64 d x 4 jc_local x 4 tq = 1024 uint2 ; 4 per thread
#pragma unroll
    for (int r = 0; r < 4; ++r) {
        int lin = r * 256 + tid;          // d(6) | jcl(2) | tq(2)
        int tq = lin & 3, jcl = (lin >> 2) & 3, d = lin >> 4;
        int jl = jcl * 16 + 2 * tq;
        __half2 x = __floats2half2_rn(tile[jl * 65 + d],       tile[(jl + 1) * 65 + d]);
        __half2 y = __floats2half2_rn(tile[(jl + 8) * 65 + d], tile[(jl + 9) * 65 + d]);
        uint2 o; o.x = *(unsigned*)&x; o.y = *(unsigned*)&y;
        int n = b * 64 + d;
        int jc = (j0 >> 4) + jcl;
        g_hT2[((size_t)n * 256 + jc) * 4 + tq] = o;
    }
}

// ---------------------------------------------------------------------------
// colsum + base + dalpha tables. Grid = 8 (one block per b).
// ---------------------------------------------------------------------------
__global__ void __launch_bounds__(256) prep_kernel(const float* __restrict__ h,
                                                   const float* __restrict__ alpha) {
    __shared__ float red[256];
    const int b = blockIdx.x, tid = threadIdx.x, d = tid & 63, jg = tid >> 6;
    float s = 0.f;
    for (int j = jg; j < NN; j += 4) s += h[((size_t)b * NN + j) * DD + d];
    red[tid] = s;
    __syncthreads();
    if (jg == 0)
        g_base[b * 64 + d] = alpha[7 * 64 + d] * (red[d] + red[64 + d] + red[128 + d] + red[192 + d]);
    if (b == 0) {
        for (int t = tid; t < 7 * 512; t += 256) {
            int k = t >> 9, dd = t & 63;
            unsigned short us = __half_as_ushort(
                __float2half_rn(alpha[k * 64 + dd] - alpha[7 * 64 + dd]));
            g_scl[t] = (unsigned)us | ((unsigned)us << 16);
        }
    }
}

// ---------------------------------------------------------------------------
static __device__ __forceinline__ void mma16816(float* c, unsigned a0, unsigned a1,
                                                unsigned a2, unsigned a3,
                                                unsigned b0, unsigned b1) {
    asm volatile(
        "mma.sync.aligned.m16n8k16.row.col.f32.f16.f16.f32 "
        "{%0,%1,%2,%3},{%4,%5,%6,%7},{%8,%9},{%0,%1,%2,%3};"
        : "+f"(c[0]), "+f"(c[1]), "+f"(c[2]), "+f"(c[3])
        : "r"(a0), "r"(a1), "r"(a2), "r"(a3), "r"(b0), "r"(b1));
}
static __device__ __forceinline__ unsigned heq2u(unsigned a, unsigned kh2) {
    __half2 r = __heq2(*(__half2*)&a, *(__half2*)&kh2);   // 1.0 / 0.0 per half
    return *(unsigned*)&r;
}
static __device__ __forceinline__ unsigned hmul2u(unsigned a, unsigned b) {
    __half2 r = __hmul2(*(__half2*)&a, *(__half2*)&b);
    return *(unsigned*)&r;
}

struct Buf { uint2 b0, b8; uint2 h[8]; };

static __device__ __forceinline__ void loadbuf(Buf& B, const uint2* bp0, const uint2* bp8,
                                               const uint2* hb, int jc) {
    const int o = jc * 4;
    B.b0 = bp0[o];
    B.b8 = bp8[o];
#pragma unroll
    for (int t = 0; t < 8; ++t) B.h[t] = hb[(size_t)t * 8192 + o];   // t stride: 8 n-rows
}

static __device__ __forceinline__ void compute(const Buf& B, const unsigned* kh2,
                                               const unsigned scl[7][8], float acc[8][4]) {
#pragma unroll
    for (int k = 0; k < 7; ++k) {
        const unsigned a0 = heq2u(B.b0.x, kh2[k]);   // row g,   cols 2tq..+1
        const unsigned a1 = heq2u(B.b8.x, kh2[k]);   // row g+8, cols 2tq..+1
        const unsigned a2 = heq2u(B.b0.y, kh2[k]);   // row g,   cols +8
        const unsigned a3 = heq2u(B.b8.y, kh2[k]);   // row g+8, cols +8
#pragma unroll
        for (int t = 0; t < 8; ++t) {
            const unsigned b0 = hmul2u(B.h[t].x, scl[k][t]);
            const unsigned b1 = hmul2u(B.h[t].y, scl[k][t]);
            mma16816(acc[t], a0, a1, a2, a3, b0, b1);
        }
    }
}

// ---------------------------------------------------------------------------
// Main: grid 256 (i-tiles of 16), 256 thr, no smem, no syncs.
// Warp w owns n in [w*64, w*64+64); lane (g = l>>2, tq = l&3).
// 2-chunk unrolled software pipeline (explicit double buffer).
// ---------------------------------------------------------------------------
__global__ void __launch_bounds__(256, 1) mix_mma_kernel(float* __restrict__ out) {
    const int tid = threadIdx.x, w = tid >> 5, l = tid & 31;
    const int g = l >> 2, tq = l & 3;
    const int i0 = blockIdx.x * 16;

    // fp16 constants k = 0..6 as half2{k,k}
    unsigned kh2[7];
#pragma unroll
    for (int k = 0; k < 7; ++k) {
        __half2 v = __floats2half2_rn((float)k, (float)k);
        kh2[k] = *(unsigned*)&v;
    }
    // per-lane dalpha half2 scales: n = w*64 + t*8 + g
    unsigned scl[7][8];
#pragma unroll
    for (int k = 0; k < 7; ++k)
#pragma unroll
        for (int t = 0; t < 8; ++t)
            scl[k][t] = g_scl[k * 512 + w * 64 + t * 8 + g];

    float acc[8][4];
#pragma unroll
    for (int t = 0; t < 8; ++t)
#pragma unroll
        for (int q = 0; q < 4; ++q) acc[t][q] = 0.f;

    const uint2* bp0 = g_bph + ((size_t)(i0 + g) * 256) * 4 + tq;
    const uint2* bp8 = g_bph + ((size_t)(i0 + g + 8) * 256) * 4 + tq;
    const uint2* hb  = g_hT2 + ((size_t)(w * 64 + g) * 256) * 4 + tq;

    Buf A, Bv;
    loadbuf(A, bp0, bp8, hb, 0);

    for (int jc = 0; jc < 256; jc += 2) {
        loadbuf(Bv, bp0, bp8, hb, (jc + 1) & 255);
        compute(A, kh2, scl, acc);
        loadbuf(A, bp0, bp8, hb, (jc + 2) & 255);
        compute(Bv, kh2, scl, acc);
    }

    // epilogue: b = w; rows i0+g (acc[.][0..1]) and i0+g+8 (acc[.][2..3]);
    // cols d = t*8 + 2tq, +1.
#pragma unroll
    for (int t = 0; t < 8; ++t) {
        const int n0 = w * 64 + t * 8 + 2 * tq;
        const float2 base = *(const float2*)&g_base[n0];
        const int dcol = t * 8 + 2 * tq;
        float2 v0 = make_float2(acc[t][0] + base.x, acc[t][1] + base.y);
        float2 v1 = make_float2(acc[t][2] + base.x, acc[t][3] + base.y);
        *(float2*)&out[((size_t)w * NN + i0 + g) * DD + dcol]     = v0;
        *(float2*)&out[((size_t)w * NN + i0 + g + 8) * DD + dcol] = v1;
    }
}

// ---------------------------------------------------------------------------
extern "C" void kernel_launch(void* const* d_in, const int* in_sizes, int n_in,
                              void* d_out, int out_size) {
    const float* h = nullptr;
    const void*  spd = nullptr;
    const float* alpha = nullptr;
    for (int i = 0; i < n_in; ++i) {
        if (in_sizes[i] == BB * NN * DD)      h     = (const float*)d_in[i];
        else if (in_sizes[i] == NN * NN)      spd   = (const void*)d_in[i];
        else if (in_sizes[i] == 8 * DD)       alpha = (const float*)d_in[i];
    }

    convert_spd_kernel<<<(int)(((size_t)NN * 1024) / 256), 256>>>((const unsigned int*)spd);
    transpose_h_kernel<<<BB * 64, 256>>>(h);
    prep_kernel<<<BB, 256>>>(h, alpha);
    mix_mma_kernel<<<NN / 16, 256>>>((float*)d_out);
}

// round 16
// speedup vs baseline: 1.4120x; 1.0051x over previous
#include <cuda_runtime.h>
#include <cuda_fp16.h>
#include <cstdint>

// DistTokenMix: out[b,i,d] = sum_j h[b,j,d] * alpha[spd[i,j], d]
//  = sum_{k<7} mask_k @ (h * (alpha_k - alpha_7)) + alpha_7[d]*colsum_j(h[b,:,d])
// Portable mma.sync.m16n8k16 (plain sm_103 target: no tcgen05).
// B=8, N=4096, D=64, buckets=8; n = b*64+d in [0,512).

#define NN 4096
#define BB 8
#define DD 64

// Buckets as fp16 pairs, chunk layout: idx ((i*256 + jc)*4 + tq) ->
//   .x = half2(spd(i, 16jc+2tq), +1),  .y = half2(16jc+2tq+8, +9)      (32 MB)
__device__ uint2 g_bph[(size_t)NN * 1024];
// hT fp16, same chunk layout over n: ((n*256 + jc)*4 + tq) -> 4 j values (8 MB)
__device__ uint2 g_hT2[(size_t)512 * 1024];
__device__ unsigned int g_scl[7 * 512];   // half2{da,da}, da = alpha_k - alpha_7
__device__ float g_base[512];             // alpha7[d] * colsum[b,d]

// ---------------------------------------------------------------------------
// spd (int64 OR int32, runtime-detected) -> fp16 bucket-pair table.
// ---------------------------------------------------------------------------
__global__ void __launch_bounds__(256) convert_spd_kernel(const unsigned int* __restrict__ spd_raw) {
    __shared__ int s_is64;
    if (threadIdx.x == 0) {
        unsigned int orv = 0;
#pragma unroll
        for (int t = 1; t < 64; t += 2) orv |= spd_raw[t];
        s_is64 = (orv == 0u) ? 1 : 0;     // int64 small values: odd words all 0
    }
    __syncthreads();
    const bool is64 = (s_is64 != 0);
    size_t idx = (size_t)blockIdx.x * 256 + threadIdx.x;   // over NN*1024
    int i  = (int)(idx >> 10);
    int e  = (int)(idx & 1023);
    int jc = e >> 2, tq = e & 3;
    int j0 = jc * 16 + 2 * tq;
    unsigned v[4];
#pragma unroll
    for (int c = 0; c < 4; ++c) {
        int j = j0 + ((c >> 1) * 8) + (c & 1);             // j0, j0+1, j0+8, j0+9
        long long off = (long long)i * NN + j;
        v[c] = (is64 ? spd_raw[off * 2] : spd_raw[off]) & 7u;
    }
    uint2 r;
    __half2 x = __floats2half2_rn((float)v[0], (float)v[1]);
    __half2 y = __floats2half2_rn((float)v[2], (float)v[3]);
    r.x = *(unsigned*)&x;
    r.y = *(unsigned*)&y;
    g_bph[idx] = r;
}

// ---------------------------------------------------------------------------
// h[b,j,d] f32 -> g_hT2 fp16 chunk layout.
// ---------------------------------------------------------------------------
__global__ void __launch_bounds__(256) transpose_h_kernel(const float* __restrict__ h) {
    __shared__ float tile[64 * 65];       // [jj][d]
    const int b = blockIdx.x >> 6, j0 = (blockIdx.x & 63) * 64, tid = threadIdx.x;
#pragma unroll
    for (int r = 0; r < 16; ++r) {
        int lin = r * 256 + tid, d = lin & 63, jj = lin >> 6;
        tile[jj * 65 + d] = h[((size_t)b * NN + j0 + jj) * DD + d];
    }
    __syncthreads();
#pragma unroll
    for (int r = 0; r < 4; ++r) {
        int lin = r * 256 + tid;          // d(6) | jcl(2) | tq(2)
        int tq = lin & 3, jcl = (lin >> 2) & 3, d = lin >> 4;
        int jl = jcl * 16 + 2 * tq;
        __half2 x = __floats2half2_rn(tile[jl * 65 + d],       tile[(jl + 1) * 65 + d]);
        __half2 y = __floats2half2_rn(tile[(jl + 8) * 65 + d], tile[(jl + 9) * 65 + d]);
        uint2 o; o.x = *(unsigned*)&x; o.y = *(unsigned*)&y;
        int n = b * 64 + d;
        int jc = (j0 >> 4) + jcl;
        g_hT2[((size_t)n * 256 + jc) * 4 + tq] = o;
    }
}

// ---------------------------------------------------------------------------
// colsum + base + dalpha tables. Grid = 8 (one block per b).
// ---------------------------------------------------------------------------
__global__ void __launch_bounds__(256) prep_kernel(const float* __restrict__ h,
                                                   const float* __restrict__ alpha) {
    __shared__ float red[256];
    const int b = blockIdx.x, tid = threadIdx.x, d = tid & 63, jg = tid >> 6;
    float s = 0.f;
    for (int j = jg; j < NN; j += 4) s += h[((size_t)b * NN + j) * DD + d];
    red[tid] = s;
    __syncthreads();
    if (jg == 0)
        g_base[b * 64 + d] = alpha[7 * 64 + d] * (red[d] + red[64 + d] + red[128 + d] + red[192 + d]);
    if (b == 0) {
        for (int t = tid; t < 7 * 512; t += 256) {
            int k = t >> 9, dd = t & 63;
            unsigned short us = __half_as_ushort(
                __float2half_rn(alpha[k * 64 + dd] - alpha[7 * 64 + dd]));
            g_scl[t] = (unsigned)us | ((unsigned)us << 16);
        }
    }
}

// ---------------------------------------------------------------------------
static __device__ __forceinline__ void mma16816(float* c, unsigned a0, unsigned a1,
                                                unsigned a2, unsigned a3,
                                                unsigned b0, unsigned b1) {
    asm volatile(
        "mma.sync.aligned.m16n8k16.row.col.f32.f16.f16.f32 "
        "{%0,%1,%2,%3},{%4,%5,%6,%7},{%8,%9},{%0,%1,%2,%3};"
        : "+f"(c[0]), "+f"(c[1]), "+f"(c[2]), "+f"(c[3])
        : "r"(a0), "r"(a1), "r"(a2), "r"(a3), "r"(b0), "r"(b1));
}
static __device__ __forceinline__ unsigned heq2u(unsigned a, unsigned kh2) {
    __half2 r = __heq2(*(__half2*)&a, *(__half2*)&kh2);   // 1.0 / 0.0 per half
    return *(unsigned*)&r;
}
static __device__ __forceinline__ unsigned hmul2u(unsigned a, unsigned b) {
    __half2 r = __hmul2(*(__half2*)&a, *(__half2*)&b);
    return *(unsigned*)&r;
}

struct Buf { uint2 b0, b8; uint2 h[4]; };

static __device__ __forceinline__ void loadbuf(Buf& B, const uint2* bp0, const uint2* bp8,
                                               const uint2* hb, int jc) {
    const int o = jc * 4;
    B.b0 = bp0[o];
    B.b8 = bp8[o];
#pragma unroll
    for (int t = 0; t < 4; ++t) B.h[t] = hb[(size_t)t * 8192 + o];   // t stride: 8 n-rows
}

static __device__ __forceinline__ void compute(const Buf& B, const unsigned* kh2,
                                               const unsigned scl[7][4], float acc[4][4]) {
#pragma unroll
    for (int k = 0; k < 7; ++k) {
        const unsigned a0 = heq2u(B.b0.x, kh2[k]);   // row g,   cols 2tq..+1
        const unsigned a1 = heq2u(B.b8.x, kh2[k]);   // row g+8, cols 2tq..+1
        const unsigned a2 = heq2u(B.b0.y, kh2[k]);   // row g,   cols +8
        const unsigned a3 = heq2u(B.b8.y, kh2[k]);   // row g+8, cols +8
#pragma unroll
        for (int t = 0; t < 4; ++t) {
            const unsigned b0 = hmul2u(B.h[t].x, scl[k][t]);
            const unsigned b1 = hmul2u(B.h[t].y, scl[k][t]);
            mma16816(acc[t], a0, a1, a2, a3, b0, b1);
        }
    }
}

// ---------------------------------------------------------------------------
// Main: grid 512 = (256 i-tiles of 16) x (2 n-halves); 256 thr; 2 CTAs/SM
// (<=128 regs) -> 4 warps/SMSP. Warp w owns n in [nh*256 + w*32, +32);
// lane (g = l>>2, tq = l&3). 2-chunk unrolled software pipeline.
// ---------------------------------------------------------------------------
__global__ void __launch_bounds__(256, 2) mix_mma_kernel(float* __restrict__ out) {
    const int tid = threadIdx.x, w = tid >> 5, l = tid & 31;
    const int g = l >> 2, tq = l & 3;
    const int i0 = (blockIdx.x >> 1) * 16;
    const int nh = blockIdx.x & 1;
    const int nwb = nh * 256 + w * 32;       // warp n-base

    // fp16 constants k = 0..6 as half2{k,k}
    unsigned kh2[7];
#pragma unroll
    for (int k = 0; k < 7; ++k) {
        __half2 v = __floats2half2_rn((float)k, (float)k);
        kh2[k] = *(unsigned*)&v;
    }
    // per-lane dalpha half2 scales: n = nwb + t*8 + g
    unsigned scl[7][4];
#pragma unroll
    for (int k = 0; k < 7; ++k)
#pragma unroll
        for (int t = 0; t < 4; ++t)
            scl[k][t] = g_scl[k * 512 + nwb + t * 8 + g];

    float acc[4][4];
#pragma unroll
    for (int t = 0; t < 4; ++t)
#pragma unroll
        for (int q = 0; q < 4; ++q) acc[t][q] = 0.f;

    const uint2* bp0 = g_bph + ((size_t)(i0 + g) * 256) * 4 + tq;
    const uint2* bp8 = g_bph + ((size_t)(i0 + g + 8) * 256) * 4 + tq;
    const uint2* hb  = g_hT2 + ((size_t)(nwb + g) * 256) * 4 + tq;

    Buf A, Bv;
    loadbuf(A, bp0, bp8, hb, 0);

    for (int jc = 0; jc < 256; jc += 2) {
        loadbuf(Bv, bp0, bp8, hb, (jc + 1) & 255);
        compute(A, kh2, scl, acc);
        loadbuf(A, bp0, bp8, hb, (jc + 2) & 255);
        compute(Bv, kh2, scl, acc);
    }

    // epilogue: rows i0+g (acc[.][0..1]) and i0+g+8 (acc[.][2..3]);
    // lane cols n = nwb + t*8 + 2tq (+1); b = n>>6, d = n&63.
#pragma unroll
    for (int t = 0; t < 4; ++t) {
        const int n0 = nwb + t * 8 + 2 * tq;
        const int b = n0 >> 6, d = n0 & 63;
        const float2 base = *(const float2*)&g_base[n0];
        float2 v0 = make_float2(acc[t][0] + base.x, acc[t][1] + base.y);
        float2 v1 = make_float2(acc[t][2] + base.x, acc[t][3] + base.y);
        *(float2*)&out[((size_t)b * NN + i0 + g) * DD + d]     = v0;
        *(float2*)&out[((size_t)b * NN + i0 + g + 8) * DD + d] = v1;
    }
}

// ---------------------------------------------------------------------------
extern "C" void kernel_launch(void* const* d_in, const int* in_sizes, int n_in,
                              void* d_out, int out_size) {
    const float* h = nullptr;
    const void*  spd = nullptr;
    const float* alpha = nullptr;
    for (int i = 0; i < n_in; ++i) {
        if (in_sizes[i] == BB * NN * DD)      h     = (const float*)d_in[i];
        else if (in_sizes[i] == NN * NN)      spd   = (const void*)d_in[i];
        else if (in_sizes[i] == 8 * DD)       alpha = (const float*)d_in[i];
    }

    convert_spd_kernel<<<(int)(((size_t)NN * 1024) / 256), 256>>>((const unsigned int*)spd);
    transpose_h_kernel<<<BB * 64, 256>>>(h);
    prep_kernel<<<BB, 256>>>(h, alpha);
    mix_mma_kernel<<<NN / 16 * 2, 256>>>((float*)d_out);
}